// round 1
// baseline (speedup 1.0000x reference)
#include <cuda_runtime.h>
#include <math.h>

#define BB 8
#define NN 400
#define DD 768
#define CC 3
#define MM 160
#define NPAIR (MM*(MM-1))      // 25440
#define PROB_ELEMS (BB*NPAIR*CC)   // 610560

// ---------------- scratch (static device globals; no allocation) ----------------
__device__ double g_s[BB*NN];
__device__ int    g_pos[BB*MM];
__device__ float  g_xr[BB*MM*DD];
__device__ int    g_rr[BB*MM*2];
__device__ float  g_ab[BB*MM*6];   // a[0..2], b[0..2] per (b,m), no bias

// ---------------- K1: span dot (double accumulation for exact ordering) --------
__global__ void k_span(const float* __restrict__ x, const float* __restrict__ w) {
    int b = blockIdx.x / NN, n = blockIdx.x % NN;
    const float* xr = x + (size_t)(b*NN + n) * DD;
    double acc = 0.0;
    for (int d = threadIdx.x; d < DD; d += blockDim.x)
        acc += (double)xr[d] * (double)w[d];
    __shared__ double sh[4];
    #pragma unroll
    for (int o = 16; o; o >>= 1) acc += __shfl_down_sync(0xffffffffu, acc, o);
    if ((threadIdx.x & 31) == 0) sh[threadIdx.x >> 5] = acc;
    __syncthreads();
    if (threadIdx.x == 0)
        g_s[b*NN + n] = sh[0] + sh[1] + sh[2] + sh[3];
}

// ---------------- K2: rank + position selection --------------------------------
// order = argsort(-h) (stable). pos = ascending sorted { rank(i) : i < M }.
__global__ void k_select() {
    int b = blockIdx.x;
    __shared__ double sh[NN];
    __shared__ int flags[NN];
    int t = threadIdx.x;
    if (t < NN) { sh[t] = g_s[b*NN + t]; flags[t] = 0; }
    __syncthreads();
    if (t < NN) {
        double v = sh[t];
        int rank = 0;
        for (int k = 0; k < NN; k++) {
            double u = sh[k];
            rank += (u > v) || (u == v && k < t);
        }
        if (t < MM) flags[rank] = 1;
    }
    __syncthreads();
    if (t == 0) {
        int c = 0;
        for (int j = 0; j < NN; j++)
            if (flags[j]) g_pos[b*MM + (c++)] = j;
    }
}

// ---------------- K3: gather x_ranked, ranges, and a/b projections -------------
__global__ void k_gather(const float* __restrict__ x, const float* __restrict__ wp,
                         const int* __restrict__ ranges) {
    int m = blockIdx.x, b = blockIdx.y;
    int p = g_pos[b*MM + m];
    const float4* src = (const float4*)(x + (size_t)(b*NN + p) * DD);
    float4* dst = (float4*)(g_xr + (size_t)(b*MM + m) * DD);
    float acc[6] = {0,0,0,0,0,0};
    for (int t = threadIdx.x; t < DD/4; t += blockDim.x) {
        float4 v = src[t];
        dst[t] = v;
        int d = t * 4;
        float vv[4] = {v.x, v.y, v.z, v.w};
        #pragma unroll
        for (int q = 0; q < 4; q++) {
            #pragma unroll
            for (int c = 0; c < CC; c++) {
                acc[c]     += vv[q] * wp[(d + q) * CC + c];
                acc[3 + c] += vv[q] * wp[(DD + d + q) * CC + c];
            }
        }
    }
    __shared__ float sh[6][4];
    #pragma unroll
    for (int r = 0; r < 6; r++) {
        float a = acc[r];
        #pragma unroll
        for (int o = 16; o; o >>= 1) a += __shfl_down_sync(0xffffffffu, a, o);
        if ((threadIdx.x & 31) == 0) sh[r][threadIdx.x >> 5] = a;
    }
    __syncthreads();
    if (threadIdx.x < 6)
        g_ab[(b*MM + m)*6 + threadIdx.x] =
            sh[threadIdx.x][0] + sh[threadIdx.x][1] + sh[threadIdx.x][2] + sh[threadIdx.x][3];
    if (threadIdx.x < 2)
        g_rr[(b*MM + m)*2 + threadIdx.x] = ranges[p*2 + threadIdx.x];
}

// ---------------- K4: pairwise logits + sigmoid + softmax + gather -------------
// tile: 16 (i) x 32 (j); 128 threads; 2x2 micro per thread; d-chunks of 64.
#define TI 16
#define TJ 32
#define DCH 64

__global__ void __launch_bounds__(128)
k_pairs(const float* __restrict__ wp, const float* __restrict__ bpair,
        float* __restrict__ out) {
    __shared__ float Xi[TI][DCH + 1];
    __shared__ float Xj[TJ][DCH + 1];
    __shared__ float W[CC][DCH];

    int b = blockIdx.y;
    int ibase = (blockIdx.x % 10) * TI;
    int jbase = (blockIdx.x / 10) * TJ;
    int tid = threadIdx.x;
    int tj = tid & 15;        // 0..15 -> j pair
    int ti = tid >> 4;        // 0..7  -> i pair

    float acc[2][2][3];
    #pragma unroll
    for (int a = 0; a < 2; a++)
        #pragma unroll
        for (int c = 0; c < 2; c++)
            #pragma unroll
            for (int k = 0; k < 3; k++) acc[a][c][k] = 0.f;

    const float* xrb = g_xr + (size_t)b * MM * DD;

    for (int ch = 0; ch < DD / DCH; ch++) {
        int dbase = ch * DCH;
        // load Xi: 16 rows x 16 float4
        #pragma unroll
        for (int e = tid; e < TI * (DCH/4); e += 128) {
            int r = e >> 4, c4 = e & 15;
            float4 v = *(const float4*)(xrb + (size_t)(ibase + r) * DD + dbase + c4 * 4);
            Xi[r][c4*4+0] = v.x; Xi[r][c4*4+1] = v.y; Xi[r][c4*4+2] = v.z; Xi[r][c4*4+3] = v.w;
        }
        // load Xj: 32 rows x 16 float4
        #pragma unroll
        for (int e = tid; e < TJ * (DCH/4); e += 128) {
            int r = e >> 4, c4 = e & 15;
            float4 v = *(const float4*)(xrb + (size_t)(jbase + r) * DD + dbase + c4 * 4);
            Xj[r][c4*4+0] = v.x; Xj[r][c4*4+1] = v.y; Xj[r][c4*4+2] = v.z; Xj[r][c4*4+3] = v.w;
        }
        // load transposed w3 chunk
        if (tid < DCH) {
            int d = dbase + tid;
            W[0][tid] = wp[(2*DD + d)*CC + 0];
            W[1][tid] = wp[(2*DD + d)*CC + 1];
            W[2][tid] = wp[(2*DD + d)*CC + 2];
        }
        __syncthreads();

        #pragma unroll 16
        for (int dd = 0; dd < DCH; dd++) {
            float w0 = W[0][dd], w1 = W[1][dd], w2 = W[2][dd];
            float a0 = Xi[2*ti][dd],   a1 = Xi[2*ti+1][dd];
            float b0 = Xj[2*tj][dd],   b1 = Xj[2*tj+1][dd];
            float p;
            p = a0*b0; acc[0][0][0] += p*w0; acc[0][0][1] += p*w1; acc[0][0][2] += p*w2;
            p = a0*b1; acc[0][1][0] += p*w0; acc[0][1][1] += p*w1; acc[0][1][2] += p*w2;
            p = a1*b0; acc[1][0][0] += p*w0; acc[1][0][1] += p*w1; acc[1][0][2] += p*w2;
            p = a1*b1; acc[1][1][0] += p*w0; acc[1][1][1] += p*w1; acc[1][1][2] += p*w2;
        }
        __syncthreads();
    }

    float bp0 = bpair[0], bp1 = bpair[1], bp2 = bpair[2];

    #pragma unroll
    for (int ii = 0; ii < 2; ii++) {
        int gi = ibase + 2*ti + ii;
        float ai0 = g_ab[(b*MM + gi)*6 + 0];
        float ai1 = g_ab[(b*MM + gi)*6 + 1];
        float ai2 = g_ab[(b*MM + gi)*6 + 2];
        #pragma unroll
        for (int jj = 0; jj < 2; jj++) {
            int gj = jbase + 2*tj + jj;
            if (gi == gj) continue;
            float l0 = acc[ii][jj][0] + ai0 + g_ab[(b*MM + gj)*6 + 3] + bp0;
            float l1 = acc[ii][jj][1] + ai1 + g_ab[(b*MM + gj)*6 + 4] + bp1;
            float l2 = acc[ii][jj][2] + ai2 + g_ab[(b*MM + gj)*6 + 5] + bp2;
            float s0 = 1.f / (1.f + expf(-l0));
            float s1 = 1.f / (1.f + expf(-l1));
            float s2 = 1.f / (1.f + expf(-l2));
            float mx = fmaxf(s0, fmaxf(s1, s2));
            float e0 = expf(s0 - mx), e1 = expf(s1 - mx), e2 = expf(s2 - mx);
            float inv = 1.f / (e0 + e1 + e2);
            int pidx = gi * (MM - 1) + gj - (gj > gi ? 1 : 0);
            float* o = out + ((size_t)b * NPAIR + pidx) * 3;
            o[0] = e0 * inv; o[1] = e1 * inv; o[2] = e2 * inv;
        }
    }
}

// ---------------- K5: pair_ranges gather (written as numeric float) ------------
__global__ void k_ranges(float* __restrict__ out) {
    int idx = blockIdx.x * blockDim.x + threadIdx.x;
    if (idx >= BB * NPAIR) return;
    int b = idx / NPAIR;
    int p = idx % NPAIR;
    int gi = p / (MM - 1);
    int r  = p % (MM - 1);
    int gj = r + (r >= gi ? 1 : 0);
    const int* ri = &g_rr[(b*MM + gi)*2];
    const int* rj = &g_rr[(b*MM + gj)*2];
    float4 v = make_float4((float)ri[0], (float)ri[1], (float)rj[0], (float)rj[1]);
    ((float4*)(out + PROB_ELEMS))[idx] = v;
}

// ---------------- launcher ------------------------------------------------------
extern "C" void kernel_launch(void* const* d_in, const int* in_sizes, int n_in,
                              void* d_out, int out_size) {
    const float* x      = (const float*)d_in[0];
    const float* w_span = (const float*)d_in[1];
    // d_in[2] = b_span (scalar, monotonic shift: irrelevant to ordering)
    const float* w_pair = (const float*)d_in[3];
    const float* b_pair = (const float*)d_in[4];
    const int*   ranges = (const int*)d_in[5];
    float* out = (float*)d_out;

    k_span<<<BB * NN, 128>>>(x, w_span);
    k_select<<<BB, 512>>>();
    {
        dim3 g(MM, BB);
        k_gather<<<g, 128>>>(x, w_pair, ranges);
    }
    {
        dim3 g(50, BB);   // 10 i-tiles x 5 j-tiles
        k_pairs<<<g, 128>>>(w_pair, b_pair, out);
    }
    {
        int total = BB * NPAIR;
        k_ranges<<<(total + 255) / 256, 256>>>(out);
    }
}

// round 4
// speedup vs baseline: 2.7104x; 2.7104x over previous
#include <cuda_runtime.h>
#include <math.h>

#define BB 8
#define NN 400
#define DD 768
#define CC 3
#define MM 160
#define NPAIR (MM*(MM-1))          // 25440
#define PROB_ELEMS (BB*NPAIR*CC)   // 610560

// ---------------- scratch (static device globals; no allocation) ----------------
__device__ double g_s[BB*NN];
__device__ int    g_pos[BB*MM];
__device__ float  g_xr[BB*MM*DD];
__device__ int    g_rr[BB*MM*2];
__device__ float  g_ab[BB*MM*6];   // a[0..2], b[0..2] per (b,m), no bias

// ---------------- K1: span dot (double accumulation for exact ordering) --------
__global__ void k_span(const float* __restrict__ x, const float* __restrict__ w) {
    int b = blockIdx.x / NN, n = blockIdx.x % NN;
    const float* xr = x + (size_t)(b*NN + n) * DD;
    double acc = 0.0;
    for (int d = threadIdx.x; d < DD; d += blockDim.x)
        acc += (double)xr[d] * (double)w[d];
    __shared__ double sh[4];
    #pragma unroll
    for (int o = 16; o; o >>= 1) acc += __shfl_down_sync(0xffffffffu, acc, o);
    if ((threadIdx.x & 31) == 0) sh[threadIdx.x >> 5] = acc;
    __syncthreads();
    if (threadIdx.x == 0)
        g_s[b*NN + n] = sh[0] + sh[1] + sh[2] + sh[3];
}

// ---------------- K2: rank + position selection (int64 keys, parallel) ---------
__global__ void k_select() {
    int b = blockIdx.x;
    __shared__ unsigned long long key[NN];
    __shared__ int flags[NN];
    __shared__ int wsum[16];
    int t = threadIdx.x;     // 512 threads
    if (t < NN) {
        long long u = __double_as_longlong(g_s[b*NN + t]);
        unsigned long long k = (u < 0) ? ~(unsigned long long)u
                                       : ((unsigned long long)u | 0x8000000000000000ULL);
        key[t] = k;
        flags[t] = 0;
    }
    __syncthreads();
    if (t < MM) {
        unsigned long long v = key[t];
        int rank = 0;
        for (int k2 = 0; k2 < NN; k2++) {
            unsigned long long u = key[k2];
            rank += (u > v) || (u == v && k2 < t);
        }
        flags[rank] = 1;     // token t (index < M) marked at its descending rank
    }
    __syncthreads();
    // parallel compaction: pos = ascending list of set flag positions
    int f = (t < NN) ? flags[t] : 0;
    unsigned mask = __ballot_sync(0xffffffffu, f);
    int lane = t & 31, w = t >> 5;
    if (lane == 0) wsum[w] = __popc(mask);
    __syncthreads();
    if (t == 0) {
        int run = 0;
        for (int i = 0; i < 16; i++) { int c = wsum[i]; wsum[i] = run; run += c; }
    }
    __syncthreads();
    if (f) {
        int idx = wsum[w] + __popc(mask & ((1u << lane) - 1));
        g_pos[b*MM + idx] = t;
    }
}

// ---------------- K3: gather x_ranked, ranges, and a/b projections -------------
__global__ void k_gather(const float* __restrict__ x, const float* __restrict__ wp,
                         const int* __restrict__ ranges) {
    int m = blockIdx.x, b = blockIdx.y;
    int p = g_pos[b*MM + m];
    const float4* src = (const float4*)(x + (size_t)(b*NN + p) * DD);
    float4* dst = (float4*)(g_xr + (size_t)(b*MM + m) * DD);
    float acc[6] = {0,0,0,0,0,0};
    for (int t = threadIdx.x; t < DD/4; t += blockDim.x) {
        float4 v = src[t];
        dst[t] = v;
        int d = t * 4;
        float vv[4] = {v.x, v.y, v.z, v.w};
        #pragma unroll
        for (int q = 0; q < 4; q++) {
            #pragma unroll
            for (int c = 0; c < CC; c++) {
                acc[c]     += vv[q] * wp[(d + q) * CC + c];
                acc[3 + c] += vv[q] * wp[(DD + d + q) * CC + c];
            }
        }
    }
    __shared__ float sh[6][4];
    #pragma unroll
    for (int r = 0; r < 6; r++) {
        float a = acc[r];
        #pragma unroll
        for (int o = 16; o; o >>= 1) a += __shfl_down_sync(0xffffffffu, a, o);
        if ((threadIdx.x & 31) == 0) sh[r][threadIdx.x >> 5] = a;
    }
    __syncthreads();
    if (threadIdx.x < 6)
        g_ab[(b*MM + m)*6 + threadIdx.x] =
            sh[threadIdx.x][0] + sh[threadIdx.x][1] + sh[threadIdx.x][2] + sh[threadIdx.x][3];
    if (threadIdx.x < 2)
        g_rr[(b*MM + m)*2 + threadIdx.x] = ranges[p*2 + threadIdx.x];
}

// ---------------- K4: tf32 tensor-core pairwise logits + epilogue --------------
// block tile 32(i) x 32(j), 192 threads (6 warps). warp w: channel c = w%3,
// n-half nh = w/3. Each warp: C[0:32, nh*16 : nh*16+16] for its channel via
// 2x2 array of m16n8k8 tf32 mma, A = Xi * w3[:,c] (scaled in registers).
#define TILE 32
#define KCH 64
#define XS 68      // padded smem row stride (floats): bank = 4*grp + tig, conflict-free

__device__ __forceinline__ void mma_tf32(float* d,
        float a0, float a1, float a2, float a3, float b0, float b1) {
    asm volatile(
        "mma.sync.aligned.m16n8k8.row.col.f32.tf32.tf32.f32 "
        "{%0,%1,%2,%3}, {%4,%5,%6,%7}, {%8,%9}, {%0,%1,%2,%3};\n"
        : "+f"(d[0]), "+f"(d[1]), "+f"(d[2]), "+f"(d[3])
        : "r"(__float_as_uint(a0)), "r"(__float_as_uint(a1)),
          "r"(__float_as_uint(a2)), "r"(__float_as_uint(a3)),
          "r"(__float_as_uint(b0)), "r"(__float_as_uint(b1)));
}

__global__ void __launch_bounds__(192)
k_pairs(const float* __restrict__ wp, const float* __restrict__ bpair,
        float* __restrict__ out) {
    __shared__ float Xi[TILE][XS];
    __shared__ float Xj[TILE][XS];
    __shared__ float Ws[CC][KCH];
    __shared__ float Cs[CC][TILE][TILE + 1];

    int b = blockIdx.y;
    int ibase = (blockIdx.x / 5) * TILE;
    int jbase = (blockIdx.x % 5) * TILE;
    int tid = threadIdx.x;
    int wid = tid >> 5, lane = tid & 31;
    int c  = wid % 3;
    int nh = wid / 3;
    int grp = lane >> 2, tig = lane & 3;

    float acc[2][2][4];
    #pragma unroll
    for (int mi = 0; mi < 2; mi++)
        #pragma unroll
        for (int ni = 0; ni < 2; ni++)
            #pragma unroll
            for (int q = 0; q < 4; q++) acc[mi][ni][q] = 0.f;

    const float* xrb = g_xr + (size_t)b * MM * DD;

    for (int ch = 0; ch < DD / KCH; ch++) {
        int dbase = ch * KCH;
        for (int e = tid; e < TILE * (KCH/4); e += 192) {
            int r = e >> 4, c4 = e & 15;
            float4 v = *(const float4*)(xrb + (size_t)(ibase + r) * DD + dbase + c4 * 4);
            *(float4*)&Xi[r][c4 * 4] = v;
            float4 u = *(const float4*)(xrb + (size_t)(jbase + r) * DD + dbase + c4 * 4);
            *(float4*)&Xj[r][c4 * 4] = u;
        }
        if (tid < KCH) {
            int d = dbase + tid;
            Ws[0][tid] = wp[(2*DD + d)*CC + 0];
            Ws[1][tid] = wp[(2*DD + d)*CC + 1];
            Ws[2][tid] = wp[(2*DD + d)*CC + 2];
        }
        __syncthreads();

        #pragma unroll
        for (int k8 = 0; k8 < KCH / 8; k8++) {
            int kb = k8 * 8;
            float w0 = Ws[c][kb + tig], w1 = Ws[c][kb + tig + 4];
            // A fragments (Xi scaled by w3[:,c] along k)
            float a00 = Xi[grp][kb+tig]        * w0;
            float a01 = Xi[grp+8][kb+tig]      * w0;
            float a02 = Xi[grp][kb+tig+4]      * w1;
            float a03 = Xi[grp+8][kb+tig+4]    * w1;
            float a10 = Xi[16+grp][kb+tig]     * w0;
            float a11 = Xi[24+grp][kb+tig]     * w0;
            float a12 = Xi[16+grp][kb+tig+4]   * w1;
            float a13 = Xi[24+grp][kb+tig+4]   * w1;
            // B fragments: B[k][n] = Xj[n][k]
            float b00 = Xj[nh*16 + grp][kb+tig];
            float b01 = Xj[nh*16 + grp][kb+tig+4];
            float b10 = Xj[nh*16 + 8 + grp][kb+tig];
            float b11 = Xj[nh*16 + 8 + grp][kb+tig+4];

            mma_tf32(acc[0][0], a00, a01, a02, a03, b00, b01);
            mma_tf32(acc[0][1], a00, a01, a02, a03, b10, b11);
            mma_tf32(acc[1][0], a10, a11, a12, a13, b00, b01);
            mma_tf32(acc[1][1], a10, a11, a12, a13, b10, b11);
        }
        __syncthreads();
    }

    // scatter C fragments to smem for cross-warp (channel) access
    #pragma unroll
    for (int mi = 0; mi < 2; mi++)
        #pragma unroll
        for (int ni = 0; ni < 2; ni++) {
            int col = nh*16 + ni*8 + 2*tig;
            Cs[c][mi*16 + grp][col]       = acc[mi][ni][0];
            Cs[c][mi*16 + grp][col + 1]   = acc[mi][ni][1];
            Cs[c][mi*16 + grp + 8][col]     = acc[mi][ni][2];
            Cs[c][mi*16 + grp + 8][col + 1] = acc[mi][ni][3];
        }
    __syncthreads();

    float bp0 = bpair[0], bp1 = bpair[1], bp2 = bpair[2];
    for (int p = tid; p < TILE * TILE; p += 192) {
        int i = p >> 5, j = p & 31;
        int gi = ibase + i, gj = jbase + j;
        if (gi == gj) continue;
        const float* abI = &g_ab[(b*MM + gi)*6];
        const float* abJ = &g_ab[(b*MM + gj)*6];
        float l0 = Cs[0][i][j] + abI[0] + abJ[3] + bp0;
        float l1 = Cs[1][i][j] + abI[1] + abJ[4] + bp1;
        float l2 = Cs[2][i][j] + abI[2] + abJ[5] + bp2;
        float s0 = 1.f / (1.f + expf(-l0));
        float s1 = 1.f / (1.f + expf(-l1));
        float s2 = 1.f / (1.f + expf(-l2));
        float mx = fmaxf(s0, fmaxf(s1, s2));
        float e0 = expf(s0 - mx), e1 = expf(s1 - mx), e2 = expf(s2 - mx);
        float inv = 1.f / (e0 + e1 + e2);
        int pidx = gi * (MM - 1) + gj - (gj > gi ? 1 : 0);
        size_t po = (size_t)b * NPAIR + pidx;
        float* o = out + po * 3;
        o[0] = e0 * inv; o[1] = e1 * inv; o[2] = e2 * inv;
        // fused pair_ranges (as numeric floats; int values 0..39 exact)
        const int* ri = &g_rr[(b*MM + gi)*2];
        const int* rj = &g_rr[(b*MM + gj)*2];
        float4 v = make_float4((float)ri[0], (float)ri[1], (float)rj[0], (float)rj[1]);
        ((float4*)(out + PROB_ELEMS))[po] = v;
    }
}

// ---------------- launcher ------------------------------------------------------
extern "C" void kernel_launch(void* const* d_in, const int* in_sizes, int n_in,
                              void* d_out, int out_size) {
    const float* x      = (const float*)d_in[0];
    const float* w_span = (const float*)d_in[1];
    // d_in[2] = b_span (monotonic shift: irrelevant to ordering)
    const float* w_pair = (const float*)d_in[3];
    const float* b_pair = (const float*)d_in[4];
    const int*   ranges = (const int*)d_in[5];
    float* out = (float*)d_out;

    k_span<<<BB * NN, 128>>>(x, w_span);
    k_select<<<BB, 512>>>();
    {
        dim3 g(MM, BB);
        k_gather<<<g, 128>>>(x, w_pair, ranges);
    }
    {
        dim3 g(25, BB);   // 5 i-tiles x 5 j-tiles of 32
        k_pairs<<<g, 192>>>(w_pair, b_pair, out);
    }
}

// round 7
// speedup vs baseline: 2.7824x; 1.0265x over previous
#include <cuda_runtime.h>
#include <math.h>

#define BB 8
#define NN 400
#define DD 768
#define CC 3
#define MM 160
#define NPAIR (MM*(MM-1))          // 25440
#define PROB_ELEMS (BB*NPAIR*CC)   // 610560

// ---------------- scratch (static device globals; no allocation) ----------------
__device__ double g_s[BB*NN];
__device__ int    g_pos[BB*MM];
__device__ float  g_xr[BB*MM*DD];
__device__ int    g_rr[BB*MM*2];
__device__ float  g_ab[BB*MM*6];   // a[0..2], b[0..2] per (b,m), no bias

// ---------------- K1: span dot (double accumulation for exact ordering) --------
__global__ void k_span(const float* __restrict__ x, const float* __restrict__ w) {
    int b = blockIdx.x / NN, n = blockIdx.x % NN;
    const float* xr = x + (size_t)(b*NN + n) * DD;
    double acc = 0.0;
    for (int d = threadIdx.x; d < DD; d += blockDim.x)
        acc += (double)xr[d] * (double)w[d];
    __shared__ double sh[4];
    #pragma unroll
    for (int o = 16; o; o >>= 1) acc += __shfl_down_sync(0xffffffffu, acc, o);
    if ((threadIdx.x & 31) == 0) sh[threadIdx.x >> 5] = acc;
    __syncthreads();
    if (threadIdx.x == 0)
        g_s[b*NN + n] = sh[0] + sh[1] + sh[2] + sh[3];
}

// ---------------- K2: rank + position selection (int64 keys, parallel) ---------
__global__ void k_select() {
    int b = blockIdx.x;
    __shared__ unsigned long long key[NN];
    __shared__ int flags[NN];
    __shared__ int wsum[16];
    int t = threadIdx.x;     // 512 threads
    if (t < NN) {
        long long u = __double_as_longlong(g_s[b*NN + t]);
        unsigned long long k = (u < 0) ? ~(unsigned long long)u
                                       : ((unsigned long long)u | 0x8000000000000000ULL);
        key[t] = k;
        flags[t] = 0;
    }
    __syncthreads();
    if (t < MM) {
        unsigned long long v = key[t];
        int rank = 0;
        for (int k2 = 0; k2 < NN; k2++) {
            unsigned long long u = key[k2];
            rank += (u > v) || (u == v && k2 < t);
        }
        flags[rank] = 1;
    }
    __syncthreads();
    int f = (t < NN) ? flags[t] : 0;
    unsigned mask = __ballot_sync(0xffffffffu, f);
    int lane = t & 31, w = t >> 5;
    if (lane == 0) wsum[w] = __popc(mask);
    __syncthreads();
    if (t == 0) {
        int run = 0;
        for (int i = 0; i < 16; i++) { int c = wsum[i]; wsum[i] = run; run += c; }
    }
    __syncthreads();
    if (f) {
        int idx = wsum[w] + __popc(mask & ((1u << lane) - 1));
        g_pos[b*MM + idx] = t;
    }
}

// ---------------- K3: gather x_ranked, ranges, and a/b projections -------------
__global__ void k_gather(const float* __restrict__ x, const float* __restrict__ wp,
                         const int* __restrict__ ranges) {
    int m = blockIdx.x, b = blockIdx.y;
    int p = g_pos[b*MM + m];
    const float4* src = (const float4*)(x + (size_t)(b*NN + p) * DD);
    float4* dst = (float4*)(g_xr + (size_t)(b*MM + m) * DD);
    float acc[6] = {0,0,0,0,0,0};
    for (int t = threadIdx.x; t < DD/4; t += blockDim.x) {
        float4 v = src[t];
        dst[t] = v;
        int d = t * 4;
        float vv[4] = {v.x, v.y, v.z, v.w};
        #pragma unroll
        for (int q = 0; q < 4; q++) {
            #pragma unroll
            for (int c = 0; c < CC; c++) {
                acc[c]     += vv[q] * wp[(d + q) * CC + c];
                acc[3 + c] += vv[q] * wp[(DD + d + q) * CC + c];
            }
        }
    }
    __shared__ float sh[6][4];
    #pragma unroll
    for (int r = 0; r < 6; r++) {
        float a = acc[r];
        #pragma unroll
        for (int o = 16; o; o >>= 1) a += __shfl_down_sync(0xffffffffu, a, o);
        if ((threadIdx.x & 31) == 0) sh[r][threadIdx.x >> 5] = a;
    }
    __syncthreads();
    if (threadIdx.x < 6)
        g_ab[(b*MM + m)*6 + threadIdx.x] =
            sh[threadIdx.x][0] + sh[threadIdx.x][1] + sh[threadIdx.x][2] + sh[threadIdx.x][3];
    if (threadIdx.x < 2)
        g_rr[(b*MM + m)*2 + threadIdx.x] = ranges[p*2 + threadIdx.x];
}

// ---------------- K4: tf32 tensor-core pairwise logits + epilogue --------------
// block tile 32x32, 384 threads (12 warps). warp w: channel c = w%3,
// quadrant q = w/3 -> (qi,qj) 16x16 sub-tile. k-chunks of 128, 2 syncs each.
#define TILE 32
#define KCH 128
#define XS 132     // padded smem row stride: bank = 4*grp + tig -> conflict-free

__device__ __forceinline__ void mma_tf32(float* d,
        float a0, float a1, float a2, float a3, float b0, float b1) {
    asm volatile(
        "mma.sync.aligned.m16n8k8.row.col.f32.tf32.tf32.f32 "
        "{%0,%1,%2,%3}, {%4,%5,%6,%7}, {%8,%9}, {%0,%1,%2,%3};\n"
        : "+f"(d[0]), "+f"(d[1]), "+f"(d[2]), "+f"(d[3])
        : "r"(__float_as_uint(a0)), "r"(__float_as_uint(a1)),
          "r"(__float_as_uint(a2)), "r"(__float_as_uint(a3)),
          "r"(__float_as_uint(b0)), "r"(__float_as_uint(b1)));
}

__global__ void __launch_bounds__(384)
k_pairs(const float* __restrict__ wp, const float* __restrict__ bpair,
        float* __restrict__ out) {
    __shared__ float Xi[TILE][XS];
    __shared__ float Xj[TILE][XS];
    __shared__ float Ws[CC][KCH];
    __shared__ float Cs[CC][TILE][TILE + 1];

    int b = blockIdx.y;
    int ibase = (blockIdx.x / 5) * TILE;
    int jbase = (blockIdx.x % 5) * TILE;
    int tid = threadIdx.x;
    int wid = tid >> 5, lane = tid & 31;
    int c  = wid % 3;
    int quad = wid / 3;          // 0..3
    int qi = (quad & 1) * 16;
    int qj = (quad >> 1) * 16;
    int grp = lane >> 2, tig = lane & 3;

    float acc0[4] = {0,0,0,0};
    float acc1[4] = {0,0,0,0};

    const float* xrb = g_xr + (size_t)b * MM * DD;

    for (int ch = 0; ch < DD / KCH; ch++) {
        int dbase = ch * KCH;
        // load Xi, Xj: 32 rows x 32 float4 each
        for (int e = tid; e < TILE * (KCH/4); e += 384) {
            int r = e >> 5, c4 = e & 31;
            *(float4*)&Xi[r][c4 * 4] =
                *(const float4*)(xrb + (size_t)(ibase + r) * DD + dbase + c4 * 4);
            *(float4*)&Xj[r][c4 * 4] =
                *(const float4*)(xrb + (size_t)(jbase + r) * DD + dbase + c4 * 4);
        }
        // load transposed w3 chunk (3 x 128 = 384 values: one per thread)
        {
            int cc = tid >> 7, d = tid & 127;
            Ws[cc][d] = wp[(2*DD + dbase + d)*CC + cc];
        }
        __syncthreads();

        #pragma unroll
        for (int k8 = 0; k8 < KCH / 8; k8++) {
            int kb = k8 * 8;
            float w0 = Ws[c][kb + tig], w1 = Ws[c][kb + tig + 4];
            float a0 = Xi[qi + grp][kb+tig]        * w0;
            float a1 = Xi[qi + grp + 8][kb+tig]    * w0;
            float a2 = Xi[qi + grp][kb+tig+4]      * w1;
            float a3 = Xi[qi + grp + 8][kb+tig+4]  * w1;
            float b00 = Xj[qj + grp][kb+tig],     b01 = Xj[qj + grp][kb+tig+4];
            float b10 = Xj[qj + grp + 8][kb+tig], b11 = Xj[qj + grp + 8][kb+tig+4];
            mma_tf32(acc0, a0, a1, a2, a3, b00, b01);
            mma_tf32(acc1, a0, a1, a2, a3, b10, b11);
        }
        __syncthreads();
    }

    // scatter C fragments to smem for cross-warp (channel) epilogue access
    {
        int row = qi + grp, col = qj + 2*tig;
        Cs[c][row][col]         = acc0[0];
        Cs[c][row][col + 1]     = acc0[1];
        Cs[c][row + 8][col]     = acc0[2];
        Cs[c][row + 8][col + 1] = acc0[3];
        Cs[c][row][col + 8]         = acc1[0];
        Cs[c][row][col + 9]         = acc1[1];
        Cs[c][row + 8][col + 8]     = acc1[2];
        Cs[c][row + 8][col + 9]     = acc1[3];
    }
    __syncthreads();

    float bp0 = bpair[0], bp1 = bpair[1], bp2 = bpair[2];
    for (int p = tid; p < TILE * TILE; p += 384) {
        int i = p >> 5, j = p & 31;
        int gi = ibase + i, gj = jbase + j;
        if (gi == gj) continue;
        const float* abI = &g_ab[(b*MM + gi)*6];
        const float* abJ = &g_ab[(b*MM + gj)*6];
        float l0 = Cs[0][i][j] + abI[0] + abJ[3] + bp0;
        float l1 = Cs[1][i][j] + abI[1] + abJ[4] + bp1;
        float l2 = Cs[2][i][j] + abI[2] + abJ[5] + bp2;
        float s0 = 1.f / (1.f + expf(-l0));
        float s1 = 1.f / (1.f + expf(-l1));
        float s2 = 1.f / (1.f + expf(-l2));
        float mx = fmaxf(s0, fmaxf(s1, s2));
        float e0 = expf(s0 - mx), e1 = expf(s1 - mx), e2 = expf(s2 - mx);
        float inv = 1.f / (e0 + e1 + e2);
        int pidx = gi * (MM - 1) + gj - (gj > gi ? 1 : 0);
        size_t po = (size_t)b * NPAIR + pidx;
        float* o = out + po * 3;
        o[0] = e0 * inv; o[1] = e1 * inv; o[2] = e2 * inv;
        const int* ri = &g_rr[(b*MM + gi)*2];
        const int* rj = &g_rr[(b*MM + gj)*2];
        float4 v = make_float4((float)ri[0], (float)ri[1], (float)rj[0], (float)rj[1]);
        ((float4*)(out + PROB_ELEMS))[po] = v;
    }
}

// ---------------- launcher ------------------------------------------------------
extern "C" void kernel_launch(void* const* d_in, const int* in_sizes, int n_in,
                              void* d_out, int out_size) {
    const float* x      = (const float*)d_in[0];
    const float* w_span = (const float*)d_in[1];
    // d_in[2] = b_span (monotonic shift: irrelevant to ordering)
    const float* w_pair = (const float*)d_in[3];
    const float* b_pair = (const float*)d_in[4];
    const int*   ranges = (const int*)d_in[5];
    float* out = (float*)d_out;

    k_span<<<BB * NN, 128>>>(x, w_span);
    k_select<<<BB, 512>>>();
    {
        dim3 g(MM, BB);
        k_gather<<<g, 128>>>(x, w_pair, ranges);
    }
    {
        dim3 g(25, BB);   // 5 i-tiles x 5 j-tiles of 32
        k_pairs<<<g, 384>>>(w_pair, b_pair, out);
    }
}

// round 8
// speedup vs baseline: 4.1274x; 1.4834x over previous
#include <cuda_runtime.h>
#include <math.h>

#define BB 8
#define NN 400
#define DD 768
#define CC 3
#define MM 160
#define NPAIR (MM*(MM-1))          // 25440
#define PROB_ELEMS (BB*NPAIR*CC)   // 610560

// ---------------- scratch (static device globals; no allocation) ----------------
__device__ float  g_s[BB*NN];
__device__ int    g_pos[BB*MM];
__device__ float  g_xr[BB*MM*DD];
__device__ int    g_rr[BB*MM*2];
__device__ float  g_ab[BB*MM*6];   // a[0..2], b[0..2] per (b,m), no bias

// ---------------- K1: span dot (f32, warp per row) ------------------------------
__global__ void k_span(const float* __restrict__ x, const float* __restrict__ w) {
    int row = blockIdx.x * 4 + (threadIdx.x >> 5);   // 0 .. 3199
    int lane = threadIdx.x & 31;
    const float4* xr = (const float4*)(x + (size_t)row * DD);
    const float4* wr = (const float4*)w;
    float acc = 0.f;
    #pragma unroll
    for (int i = 0; i < DD/128; i++) {               // 6 iters
        float4 v = xr[i*32 + lane];
        float4 u = wr[i*32 + lane];
        acc = fmaf(v.x, u.x, acc);
        acc = fmaf(v.y, u.y, acc);
        acc = fmaf(v.z, u.z, acc);
        acc = fmaf(v.w, u.w, acc);
    }
    #pragma unroll
    for (int o = 16; o; o >>= 1) acc += __shfl_down_sync(0xffffffffu, acc, o);
    if (lane == 0) g_s[row] = acc;
}

// ---------------- K2: rank + position selection (uint32 keys, parallel) ---------
__global__ void k_select() {
    int b = blockIdx.x;
    __shared__ unsigned int key[NN];
    __shared__ int flags[NN];
    __shared__ int wsum[16];
    int t = threadIdx.x;     // 512 threads
    if (t < NN) {
        int u = __float_as_int(g_s[b*NN + t]);
        unsigned int k = (u < 0) ? ~(unsigned int)u : ((unsigned int)u | 0x80000000u);
        key[t] = k;
        flags[t] = 0;
    }
    __syncthreads();
    if (t < MM) {
        unsigned int v = key[t];
        int rank = 0;
        for (int k2 = 0; k2 < NN; k2++) {
            unsigned int u = key[k2];
            rank += (u > v) || (u == v && k2 < t);
        }
        flags[rank] = 1;
    }
    __syncthreads();
    int f = (t < NN) ? flags[t] : 0;
    unsigned mask = __ballot_sync(0xffffffffu, f);
    int lane = t & 31, w = t >> 5;
    if (lane == 0) wsum[w] = __popc(mask);
    __syncthreads();
    if (t == 0) {
        int run = 0;
        for (int i = 0; i < 16; i++) { int c = wsum[i]; wsum[i] = run; run += c; }
    }
    __syncthreads();
    if (f) {
        int idx = wsum[w] + __popc(mask & ((1u << lane) - 1));
        g_pos[b*MM + idx] = t;
    }
}

// ---------------- K3: gather x_ranked, ranges, and a/b projections -------------
__global__ void k_gather(const float* __restrict__ x, const float* __restrict__ wp,
                         const int* __restrict__ ranges) {
    int m = blockIdx.x, b = blockIdx.y;
    int p = g_pos[b*MM + m];
    const float4* src = (const float4*)(x + (size_t)(b*NN + p) * DD);
    float4* dst = (float4*)(g_xr + (size_t)(b*MM + m) * DD);
    float acc[6] = {0,0,0,0,0,0};
    for (int t = threadIdx.x; t < DD/4; t += blockDim.x) {
        float4 v = src[t];
        dst[t] = v;
        int d = t * 4;
        float vv[4] = {v.x, v.y, v.z, v.w};
        #pragma unroll
        for (int q = 0; q < 4; q++) {
            #pragma unroll
            for (int c = 0; c < CC; c++) {
                acc[c]     += vv[q] * wp[(d + q) * CC + c];
                acc[3 + c] += vv[q] * wp[(DD + d + q) * CC + c];
            }
        }
    }
    __shared__ float sh[6][4];
    #pragma unroll
    for (int r = 0; r < 6; r++) {
        float a = acc[r];
        #pragma unroll
        for (int o = 16; o; o >>= 1) a += __shfl_down_sync(0xffffffffu, a, o);
        if ((threadIdx.x & 31) == 0) sh[r][threadIdx.x >> 5] = a;
    }
    __syncthreads();
    if (threadIdx.x < 6)
        g_ab[(b*MM + m)*6 + threadIdx.x] =
            sh[threadIdx.x][0] + sh[threadIdx.x][1] + sh[threadIdx.x][2] + sh[threadIdx.x][3];
    if (threadIdx.x < 2)
        g_rr[(b*MM + m)*2 + threadIdx.x] = ranges[p*2 + threadIdx.x];
}

// ---------------- K4: tf32 tensor-core pairwise logits + epilogue --------------
// block tile 16(i) x 32(j), 192 threads (6 warps). warp w: channel c = w%3,
// j-half qj = (w/3)*16. Packed smem columns: cperm(d)=k8*8+(d&3)*2+((d>>2)&1)
// so each fragment (k, k+4) pair is one ld.shared.v2.
#define TI 16
#define TJ 32
#define KCH 128
#define XS 136     // 136 mod 32 == 8 -> grp rows hit distinct bank octets

__device__ __forceinline__ void mma_tf32(float* d,
        float a0, float a1, float a2, float a3, float b0, float b1) {
    asm volatile(
        "mma.sync.aligned.m16n8k8.row.col.f32.tf32.tf32.f32 "
        "{%0,%1,%2,%3}, {%4,%5,%6,%7}, {%8,%9}, {%0,%1,%2,%3};\n"
        : "+f"(d[0]), "+f"(d[1]), "+f"(d[2]), "+f"(d[3])
        : "r"(__float_as_uint(a0)), "r"(__float_as_uint(a1)),
          "r"(__float_as_uint(a2)), "r"(__float_as_uint(a3)),
          "r"(__float_as_uint(b0)), "r"(__float_as_uint(b1)));
}

__global__ void __launch_bounds__(192)
k_pairs(const float* __restrict__ wp, const float* __restrict__ bpair,
        float* __restrict__ out) {
    __shared__ float Xi[TI][XS];
    __shared__ float Xj[TJ][XS];
    __shared__ float Ws[CC][KCH];
    __shared__ float Cs[CC][TI][TJ + 1];

    int b = blockIdx.y;
    int ibase = (blockIdx.x / 5) * TI;
    int jbase = (blockIdx.x % 5) * TJ;
    int tid = threadIdx.x;
    int wid = tid >> 5, lane = tid & 31;
    int c  = wid % 3;
    int qj = (wid / 3) * 16;
    int grp = lane >> 2, tig = lane & 3;

    float acc0[4] = {0,0,0,0};
    float acc1[4] = {0,0,0,0};

    const float* xrb = g_xr + (size_t)b * MM * DD;

    for (int ch = 0; ch < DD / KCH; ch++) {
        int dbase = ch * KCH;
        // load Xi (16x32 float4) + Xj (32x32 float4), permuted scatter to smem
        #pragma unroll
        for (int e = tid; e < (TI + TJ) * (KCH/4); e += 192) {
            int r = e >> 5, c4 = e & 31;
            int d0 = c4 * 4;
            int pos = ((d0 >> 3) << 3) + ((d0 >> 2) & 1);  // k8*8 + half
            float* dstrow = (r < TI) ? Xi[r] : Xj[r - TI];
            const float* srcrow = xrb + (size_t)((r < TI ? ibase + r : jbase + r - TI)) * DD;
            float4 v = *(const float4*)(srcrow + dbase + d0);
            dstrow[pos]     = v.x;
            dstrow[pos + 2] = v.y;
            dstrow[pos + 4] = v.z;
            dstrow[pos + 6] = v.w;
        }
        // load transposed w3 chunk, same permutation (3 x 128 values)
        #pragma unroll
        for (int e = tid; e < CC * KCH; e += 192) {
            int cc = e >> 7, d = e & 127;
            int pos = ((d >> 3) << 3) + ((d & 3) << 1) + ((d >> 2) & 1);
            Ws[cc][pos] = wp[(2*DD + dbase + d)*CC + cc];
        }
        __syncthreads();

        #pragma unroll
        for (int k8 = 0; k8 < KCH / 8; k8++) {
            int off = k8 * 8 + tig * 2;
            float2 w  = *(const float2*)&Ws[c][off];
            float2 ai0 = *(const float2*)&Xi[grp][off];
            float2 ai1 = *(const float2*)&Xi[grp + 8][off];
            float2 bj0 = *(const float2*)&Xj[qj + grp][off];
            float2 bj1 = *(const float2*)&Xj[qj + grp + 8][off];
            float a0 = ai0.x * w.x, a1 = ai1.x * w.x;
            float a2 = ai0.y * w.y, a3 = ai1.y * w.y;
            mma_tf32(acc0, a0, a1, a2, a3, bj0.x, bj0.y);
            mma_tf32(acc1, a0, a1, a2, a3, bj1.x, bj1.y);
        }
        __syncthreads();
    }

    // scatter C fragments to smem for cross-warp (channel) epilogue access
    {
        int col = qj + 2*tig;
        Cs[c][grp][col]         = acc0[0];
        Cs[c][grp][col + 1]     = acc0[1];
        Cs[c][grp + 8][col]     = acc0[2];
        Cs[c][grp + 8][col + 1] = acc0[3];
        Cs[c][grp][col + 8]     = acc1[0];
        Cs[c][grp][col + 9]     = acc1[1];
        Cs[c][grp + 8][col + 8] = acc1[2];
        Cs[c][grp + 8][col + 9] = acc1[3];
    }
    __syncthreads();

    float bp0 = bpair[0], bp1 = bpair[1], bp2 = bpair[2];
    #pragma unroll
    for (int p = tid; p < TI * TJ; p += 192) {
        int i = p >> 5, j = p & 31;
        int gi = ibase + i, gj = jbase + j;
        if (gi == gj) continue;
        const float* abI = &g_ab[(b*MM + gi)*6];
        const float* abJ = &g_ab[(b*MM + gj)*6];
        float l0 = Cs[0][i][j] + abI[0] + abJ[3] + bp0;
        float l1 = Cs[1][i][j] + abI[1] + abJ[4] + bp1;
        float l2 = Cs[2][i][j] + abI[2] + abJ[5] + bp2;
        float s0 = 1.f / (1.f + expf(-l0));
        float s1 = 1.f / (1.f + expf(-l1));
        float s2 = 1.f / (1.f + expf(-l2));
        float mx = fmaxf(s0, fmaxf(s1, s2));
        float e0 = expf(s0 - mx), e1 = expf(s1 - mx), e2 = expf(s2 - mx);
        float inv = 1.f / (e0 + e1 + e2);
        int pidx = gi * (MM - 1) + gj - (gj > gi ? 1 : 0);
        size_t po = (size_t)b * NPAIR + pidx;
        float* o = out + po * 3;
        o[0] = e0 * inv; o[1] = e1 * inv; o[2] = e2 * inv;
        const int* ri = &g_rr[(b*MM + gi)*2];
        const int* rj = &g_rr[(b*MM + gj)*2];
        float4 v = make_float4((float)ri[0], (float)ri[1], (float)rj[0], (float)rj[1]);
        ((float4*)(out + PROB_ELEMS))[po] = v;
    }
}

// ---------------- launcher ------------------------------------------------------
extern "C" void kernel_launch(void* const* d_in, const int* in_sizes, int n_in,
                              void* d_out, int out_size) {
    const float* x      = (const float*)d_in[0];
    const float* w_span = (const float*)d_in[1];
    // d_in[2] = b_span (monotonic shift: irrelevant to ordering)
    const float* w_pair = (const float*)d_in[3];
    const float* b_pair = (const float*)d_in[4];
    const int*   ranges = (const int*)d_in[5];
    float* out = (float*)d_out;

    k_span<<<BB * NN / 4, 128>>>(x, w_span);
    k_select<<<BB, 512>>>();
    {
        dim3 g(MM, BB);
        k_gather<<<g, 128>>>(x, w_pair, ranges);
    }
    {
        dim3 g(50, BB);   // 10 i-tiles(16) x 5 j-tiles(32)
        k_pairs<<<g, 192>>>(w_pair, b_pair, out);
    }
}